// round 12
// baseline (speedup 1.0000x reference)
#include <cuda_runtime.h>
#include <cuda_bf16.h>
#include <cstdint>

#define NN 8192
#define FEAT 512
#define C 40
#define HID 1024
#define INDIM 672
#define KSPL 4
#define OSPLIT2 8
typedef unsigned long long ull;

__device__ __nv_bfloat16 g_S2[(size_t)NN * NN];   // [mtile][k][m&127] tiled-transposed
__device__ __nv_bfloat16 g_curB[(size_t)C * NN];
__device__ float g_rspart[16 * NN];
__device__ float g_dinv[NN];
__device__ float g_combT[(size_t)INDIM * NN];
__device__ uint32_t g_W1t[(size_t)INDIM * HID];
__device__ float g_part[(size_t)16 * NN * C];
__device__ float g_hT[(size_t)HID * NN];

__device__ __forceinline__ float sigf(float x) {
    float t; asm("tanh.approx.f32 %0, %1;" : "=f"(t) : "f"(0.5f * x));
    return 0.5f * t + 0.5f;
}
__device__ __forceinline__ ull pack2(float a, float b) {
    ull r; asm("mov.b64 %0, {%1, %2};" : "=l"(r) : "f"(a), "f"(b)); return r;
}
__device__ __forceinline__ void ffma2(ull& d, ull a, ull b) {
    asm("fma.rn.f32x2 %0, %1, %2, %0;" : "+l"(d) : "l"(a), "l"(b));
}
__device__ __forceinline__ uint32_t cvtf(float f) {
    uint32_t r; asm("cvt.rna.tf32.f32 %0, %1;" : "=r"(r) : "f"(f)); return r;
}
#define CPA(d, s) asm volatile("cp.async.cg.shared.global [%0], [%1], 16;" :: "r"(d), "l"(s))
#define CPCOMMIT() asm volatile("cp.async.commit_group;")
#define CPWAIT0() asm volatile("cp.async.wait_group 0;")
#define CPWAIT2() asm volatile("cp.async.wait_group 2;")

// tiled sigmoid + transpose into g_S2 + rowsum partials. grid(16 jc, 64 mt) x 256
__global__ void __launch_bounds__(256) k_sigT2(const float* __restrict__ adj) {
    __shared__ __align__(16) __nv_bfloat16 st[64 * 136];
    __shared__ float red[128 * 9];
    int t = threadIdx.x;
    int mg = t & 31, jg = t >> 5;
    int j0 = blockIdx.x * 512, m0 = blockIdx.y * 128;
    size_t mtile = blockIdx.y;
    float psum[4] = {0.f, 0.f, 0.f, 0.f};
    for (int sb = 0; sb < 8; sb++) {
        int jb = j0 + sb * 64;
        float f[4][8];
#pragma unroll
        for (int e = 0; e < 4; e++) {
            const float4* p = (const float4*)(adj + (size_t)(m0 + mg * 4 + e) * NN + jb + jg * 8);
            float4 v0 = p[0], v1 = p[1];
            f[e][0] = sigf(v0.x); f[e][1] = sigf(v0.y); f[e][2] = sigf(v0.z); f[e][3] = sigf(v0.w);
            f[e][4] = sigf(v1.x); f[e][5] = sigf(v1.y); f[e][6] = sigf(v1.z); f[e][7] = sigf(v1.w);
#pragma unroll
            for (int jj = 0; jj < 8; jj++) psum[e] += f[e][jj];
        }
        __syncthreads();
#pragma unroll
        for (int jj = 0; jj < 8; jj++) {
            __nv_bfloat162 p0 = __floats2bfloat162_rn(f[0][jj], f[1][jj]);
            __nv_bfloat162 p1 = __floats2bfloat162_rn(f[2][jj], f[3][jj]);
            uint2 wv; wv.x = *(unsigned*)&p0; wv.y = *(unsigned*)&p1;
            *(uint2*)(st + (jg * 8 + jj) * 136 + mg * 4) = wv;
        }
        __syncthreads();
#pragma unroll
        for (int p = 0; p < 4; p++) {
            int u = t + 256 * p;
            int j = u >> 4, seg = u & 15;
            uint4 v = *(const uint4*)(st + j * 136 + seg * 8);
            *(uint4*)(g_S2 + (mtile * NN + jb + j) * 128 + seg * 8) = v;
        }
    }
#pragma unroll
    for (int e = 0; e < 4; e++) red[(mg * 4 + e) * 9 + jg] = psum[e];
    __syncthreads();
    if (t < 128) {
        float s = 0.f;
#pragma unroll
        for (int q = 0; q < 8; q++) s += red[t * 9 + q];
        g_rspart[blockIdx.x * NN + m0 + t] = s;
    }
}

__global__ void k_dinv() {
    int i = blockIdx.x * 256 + threadIdx.x;
    float s = 0.f;
#pragma unroll
    for (int p = 0; p < 16; p++) s += g_rspart[p * NN + i];
    g_dinv[i] = 1.f / (s + 1e-8f);
}

__global__ void k_tX(const float* __restrict__ X) {
    __shared__ float tile[32][33];
    int k0 = blockIdx.x * 32, i0 = blockIdx.y * 32;
    int tx = threadIdx.x, ty = threadIdx.y;
#pragma unroll
    for (int r = 0; r < 4; r++)
        tile[ty + 8 * r][tx] = X[(size_t)(i0 + ty + 8 * r) * FEAT + k0 + tx];
    __syncthreads();
#pragma unroll
    for (int r = 0; r < 4; r++)
        g_combT[(size_t)(k0 + ty + 8 * r) * NN + i0 + tx] =
            __uint_as_float(cvtf(tile[tx][ty + 8 * r]));
}

__global__ void k_oh(const float* __restrict__ oh) {
    int idx = blockIdx.x * 256 + threadIdx.x;
    int i = idx / C, c = idx - i * C;
    g_curB[(size_t)c * NN + i] = __float2bfloat16(oh[idx]);
}

__global__ void k_w1c(const float* __restrict__ W1) {
    int idx = blockIdx.x * 256 + threadIdx.x;
    g_W1t[idx] = cvtf(W1[idx]);
}

// hop GEMM: streaming A (tiled-transposed S), 4-stage cp.async, K-chunk 64.
// grid(64,KSPL) x 256, dyn smem 92672
__global__ void __launch_bounds__(256, 2) k_hop_mma() {
    extern __shared__ __align__(16) char hsm[];
    int t = threadIdx.x, lane = t & 31, w = t >> 5;
    size_t bm = blockIdx.x;
    int slice = blockIdx.y;
    float acc[5][4];
#pragma unroll
    for (int n = 0; n < 5; n++)
#pragma unroll
        for (int q = 0; q < 4; q++) acc[n][q] = 0.f;
    uint32_t sb = (uint32_t)__cvta_generic_to_shared(hsm);
    uint32_t bA[4], bB[4];
#pragma unroll
    for (int s = 0; s < 4; s++) { bA[s] = sb + s * 23168; bB[s] = bA[s] + 17408; }
    uint32_t aoff = (uint32_t)(((lane >> 4) * 8 + (lane & 7)) * 272
                               + (w * 16 + ((lane >> 3) & 1) * 8) * 2);

#define HOP_PF(st, k0c) do { \
    _Pragma("unroll") \
    for (int q = 0; q < 4; q++) { \
        int idx = t + 256 * q; int k = idx >> 4, g = idx & 15; \
        CPA(bA[st] + k * 272 + g * 16, g_S2 + (bm * NN + (k0c) + k) * 128 + g * 8); \
    } \
    _Pragma("unroll") \
    for (int q = 0; q < 2; q++) { \
        int idx = t + 256 * q; \
        if (idx < 320) { int row = idx >> 3, g = idx & 7; \
            CPA(bB[st] + row * 144 + g * 16, g_curB + (size_t)row * NN + (k0c) + g * 8); } \
    } } while (0)

    int kbase = slice * 2048;
    HOP_PF(0, kbase); CPCOMMIT();
    HOP_PF(1, kbase + 64); CPCOMMIT();
    HOP_PF(2, kbase + 128); CPCOMMIT();
    for (int ch = 0; ch < 32; ch++) {
        CPWAIT2();
        __syncthreads();
        if (ch + 3 < 32) HOP_PF((ch + 3) & 3, kbase + (ch + 3) * 64);
        CPCOMMIT();
        int cb = ch & 3;
        const __nv_bfloat16* B = (const __nv_bfloat16*)(hsm + cb * 23168 + 17408);
        uint32_t ab = bA[cb] + aoff;
#pragma unroll
        for (int ks = 0; ks < 4; ks++) {
            uint32_t a0, a1, a2, a3;
            asm volatile("ldmatrix.sync.aligned.m8n8.x4.trans.shared.b16 {%0,%1,%2,%3}, [%4];"
                : "=r"(a0), "=r"(a1), "=r"(a2), "=r"(a3) : "r"(ab + ks * 4352));
#pragma unroll
            for (int nt = 0; nt < 5; nt++) {
                const uint32_t* bp = (const uint32_t*)(B + (nt * 8 + (lane >> 2)) * 72
                                                       + ks * 16 + (lane & 3) * 2);
                uint32_t b0 = bp[0], b1 = bp[4];
                asm volatile("mma.sync.aligned.m16n8k16.row.col.f32.bf16.bf16.f32 "
                    "{%0,%1,%2,%3}, {%4,%5,%6,%7}, {%8,%9}, {%0,%1,%2,%3};"
                    : "+f"(acc[nt][0]), "+f"(acc[nt][1]), "+f"(acc[nt][2]), "+f"(acc[nt][3])
                    : "r"(a0), "r"(a1), "r"(a2), "r"(a3), "r"(b0), "r"(b1));
            }
        }
    }
    int r1 = (int)bm * 128 + w * 16 + (lane >> 2);
    int cc = (lane & 3) * 2;
#pragma unroll
    for (int nt = 0; nt < 5; nt++) {
        *(float2*)(g_part + ((size_t)slice * NN + r1) * C + nt * 8 + cc)
            = make_float2(acc[nt][0], acc[nt][1]);
        *(float2*)(g_part + ((size_t)slice * NN + r1 + 8) * C + nt * 8 + cc)
            = make_float2(acc[nt][2], acc[nt][3]);
    }
}

__global__ void k_hop_epi(int hop) {
    int i = blockIdx.x * 256 + threadIdx.x;
    float v[C];
#pragma unroll
    for (int c = 0; c < C; c++) v[c] = 0.f;
#pragma unroll
    for (int s = 0; s < KSPL; s++) {
        const float4* p4 = (const float4*)(g_part + ((size_t)s * NN + i) * C);
#pragma unroll
        for (int q = 0; q < 10; q++) {
            float4 w = p4[q];
            v[4*q] += w.x; v[4*q+1] += w.y; v[4*q+2] += w.z; v[4*q+3] += w.w;
        }
    }
    float di = g_dinv[i], m = -1e30f;
#pragma unroll
    for (int c = 0; c < C; c++) { v[c] *= di; m = fmaxf(m, v[c]); }
    float sum = 0.f;
#pragma unroll
    for (int c = 0; c < C; c++) { v[c] = __expf(v[c] - m); sum += v[c]; }
    float inv = 1.f / sum;
    float* ob = g_combT + (size_t)(FEAT + hop * C) * NN + i;
#pragma unroll
    for (int c = 0; c < C; c++) {
        float r = v[c] * inv;
        ob[c * NN] = __uint_as_float(cvtf(r));
        if (hop < 3) g_curB[(size_t)c * NN + i] = __float2bfloat16(r);
    }
}

// MLP1 tf32 mma: grid(64,8) x 256, dyn smem 67584B
__global__ void __launch_bounds__(256, 2) k_mlp1(const float* __restrict__ b1) {
    extern __shared__ float dsm[];
    int t = threadIdx.x, lane = t & 31, w = t >> 5;
    int i0 = blockIdx.x * 128, o0 = blockIdx.y * 128;
    int wi = (w & 3) * 32, wo = (w >> 2) * 64;
    int t4 = lane & 3, g8 = lane >> 2;
    float acc[2][8][4];
#pragma unroll
    for (int mt = 0; mt < 2; mt++)
#pragma unroll
        for (int nt = 0; nt < 8; nt++)
#pragma unroll
            for (int q = 0; q < 4; q++) acc[mt][nt][q] = 0.f;
    uint32_t sb0 = (uint32_t)__cvta_generic_to_shared(dsm);

#define M1_PF(st, k0) do { \
    uint32_t ba = sb0 + (st) * 8448 * 4; \
    _Pragma("unroll") \
    for (int q = 0; q < 4; q++) { \
        int idx = t + 256 * q; int row = idx >> 5, g = idx & 31; \
        CPA(ba + (row * 132 + g * 4) * 4, g_combT + (size_t)((k0) + row) * NN + i0 + g * 4); \
        CPA(ba + (4224 + row * 132 + g * 4) * 4, g_W1t + (size_t)((k0) + row) * HID + o0 + g * 4); \
    } } while (0)

    M1_PF(0, 0);
    CPCOMMIT();
    for (int ck = 0; ck < 21; ck++) {
        CPWAIT0();
        __syncthreads();
        if (ck < 20) { M1_PF((ck + 1) & 1, (ck + 1) * 32); CPCOMMIT(); }
        const uint32_t* A = (const uint32_t*)(dsm + (ck & 1) * 8448);
        const uint32_t* Bs = A + 4224;
#pragma unroll
        for (int ks = 0; ks < 4; ks++) {
            int kr = ks * 8;
            uint32_t bF[8][2];
#pragma unroll
            for (int nt = 0; nt < 8; nt++) {
                bF[nt][0] = Bs[(kr + t4) * 132 + wo + nt * 8 + g8];
                bF[nt][1] = Bs[(kr + t4 + 4) * 132 + wo + nt * 8 + g8];
            }
#pragma unroll
            for (int mt = 0; mt < 2; mt++) {
                int ib = wi + mt * 16 + g8;
                uint32_t a0 = A[(kr + t4) * 132 + ib];
                uint32_t a1 = A[(kr + t4) * 132 + ib + 8];
                uint32_t a2 = A[(kr + t4 + 4) * 132 + ib];
                uint32_t a3 = A[(kr + t4 + 4) * 132 + ib + 8];
#pragma unroll
                for (int nt = 0; nt < 8; nt++) {
                    asm volatile("mma.sync.aligned.m16n8k8.row.col.f32.tf32.tf32.f32 "
                        "{%0,%1,%2,%3}, {%4,%5,%6,%7}, {%8,%9}, {%0,%1,%2,%3};"
                        : "+f"(acc[mt][nt][0]), "+f"(acc[mt][nt][1]),
                          "+f"(acc[mt][nt][2]), "+f"(acc[mt][nt][3])
                        : "r"(a0), "r"(a1), "r"(a2), "r"(a3),
                          "r"(bF[nt][0]), "r"(bF[nt][1]));
                }
            }
        }
    }
    __syncthreads();
    float* dt = dsm;
#pragma unroll
    for (int mt = 0; mt < 2; mt++)
#pragma unroll
        for (int nt = 0; nt < 8; nt++) {
            int i_ = wi + mt * 16 + g8, o_ = wo + nt * 8 + 2 * t4;
            dt[o_ * 130 + i_] = acc[mt][nt][0];
            dt[(o_ + 1) * 130 + i_] = acc[mt][nt][1];
            dt[o_ * 130 + i_ + 8] = acc[mt][nt][2];
            dt[(o_ + 1) * 130 + i_ + 8] = acc[mt][nt][3];
        }
    __syncthreads();
    for (int idx = t; idx < 16384; idx += 256) {
        int o = idx >> 7, i = idx & 127;
        float v = dt[o * 130 + i] + b1[o0 + o];
        g_hT[(size_t)(o0 + o) * NN + i0 + i] = fmaxf(v, 0.f);
    }
}

__global__ void __launch_bounds__(256, 2) k_mlp2(const float* __restrict__ W2) {
    __shared__ float s_w[128 * 40];
    int t = threadIdx.x, os = blockIdx.x;
    int i = blockIdx.y * 256 + t, o0 = os * 128;
    ull acc[20];
#pragma unroll
    for (int p = 0; p < 20; p++) acc[p] = 0;
    const float4* w4 = (const float4*)W2;
#pragma unroll
    for (int idx = t; idx < 128 * 10; idx += 256)
        ((float4*)s_w)[idx] = w4[(size_t)o0 * 10 + idx];
    __syncthreads();
    const float* hb = g_hT + (size_t)o0 * NN + i;
#pragma unroll 2
    for (int o = 0; o < 128; o++) {
        float x = hb[(size_t)o * NN];
        ull x2 = pack2(x, x);
        const ull* wr = (const ull*)(s_w + o * 40);
#pragma unroll
        for (int p = 0; p < 20; p++) ffma2(acc[p], x2, wr[p]);
    }
    ull* ob = (ull*)(g_part + ((size_t)os * NN + i) * C);
#pragma unroll
    for (int p = 0; p < 20; p++) ob[p] = acc[p];
}

__global__ void k_outf(const float* __restrict__ b2, float* __restrict__ out) {
    int i = blockIdx.x * 256 + threadIdx.x;
    float v[C];
#pragma unroll
    for (int c = 0; c < C; c++) v[c] = b2[c];
#pragma unroll
    for (int s = 0; s < OSPLIT2; s++) {
        const float4* p4 = (const float4*)(g_part + ((size_t)s * NN + i) * C);
#pragma unroll
        for (int q = 0; q < 10; q++) {
            float4 w = p4[q];
            v[4*q] += w.x; v[4*q+1] += w.y; v[4*q+2] += w.z; v[4*q+3] += w.w;
        }
    }
    float4* ob = (float4*)(out + (size_t)i * C);
#pragma unroll
    for (int q = 0; q < 10; q++)
        ob[q] = make_float4(v[4*q], v[4*q+1], v[4*q+2], v[4*q+3]);
}

extern "C" void kernel_launch(void* const* d_in, const int* in_sizes, int n_in,
                              void* d_out, int out_size) {
    const float* X   = (const float*)d_in[0];
    const float* oh  = (const float*)d_in[1];
    const float* adj = (const float*)d_in[2];
    const float* W1  = (const float*)d_in[3];
    const float* b1  = (const float*)d_in[4];
    const float* W2  = (const float*)d_in[5];
    const float* b2  = (const float*)d_in[6];
    float* out = (float*)d_out;

    cudaFuncSetAttribute(k_hop_mma, cudaFuncAttributeMaxDynamicSharedMemorySize, 92672);
    cudaFuncSetAttribute(k_mlp1, cudaFuncAttributeMaxDynamicSharedMemorySize, 67584);

    k_sigT2<<<dim3(16, 64), 256>>>(adj);
    k_dinv<<<32, 256>>>();
    k_tX<<<dim3(16, 256), dim3(32, 8)>>>(X);
    k_oh<<<1280, 256>>>(oh);
    k_w1c<<<2688, 256>>>(W1);
    for (int hop = 0; hop < 4; hop++) {
        k_hop_mma<<<dim3(64, KSPL), 256, 92672>>>();
        k_hop_epi<<<32, 256>>>(hop);
    }
    k_mlp1<<<dim3(64, 8), 256, 67584>>>(b1);
    k_mlp2<<<dim3(OSPLIT2, 32), 256>>>(W2);
    k_outf<<<32, 256>>>(b2, out);
}

// round 17
// speedup vs baseline: 1.1320x; 1.1320x over previous
#include <cuda_runtime.h>
#include <cuda_bf16.h>
#include <cstdint>

#define NN 8192
#define FEAT 512
#define C 40
#define HID 1024
#define INDIM 672
#define KSPL 4
#define OSPLIT2 8
typedef unsigned long long ull;

__device__ __nv_bfloat16 g_S[(size_t)NN * NN];
__device__ __nv_bfloat16 g_curB[(size_t)C * NN];   // current distribution, bf16 [c][node]
__device__ float g_dinv[NN];
__device__ float g_combT[(size_t)INDIM * NN];      // [k][i], tf32-rounded fp32
__device__ uint32_t g_W1t[(size_t)INDIM * HID];    // W1 tf32-rounded
__device__ float g_part[(size_t)16 * NN * C];
__device__ float g_hT[(size_t)HID * NN];

__device__ __forceinline__ float sigf(float x) {
    float t; asm("tanh.approx.f32 %0, %1;" : "=f"(t) : "f"(0.5f * x));
    return 0.5f * t + 0.5f;
}
__device__ __forceinline__ ull pack2(float a, float b) {
    ull r; asm("mov.b64 %0, {%1, %2};" : "=l"(r) : "f"(a), "f"(b)); return r;
}
__device__ __forceinline__ void ffma2(ull& d, ull a, ull b) {
    asm("fma.rn.f32x2 %0, %1, %2, %0;" : "+l"(d) : "l"(a), "l"(b));
}
__device__ __forceinline__ uint32_t cvtf(float f) {
    uint32_t r; asm("cvt.rna.tf32.f32 %0, %1;" : "=r"(r) : "f"(f)); return r;
}
#define CPA(d, s) asm volatile("cp.async.cg.shared.global [%0], [%1], 16;" :: "r"(d), "l"(s))
#define CPCOMMIT() asm volatile("cp.async.commit_group;")
#define CPWAIT0() asm volatile("cp.async.wait_group 0;")
#define CPWAIT2() asm volatile("cp.async.wait_group 2;")

// sigmoid -> bf16 + fused rowsum/dinv. one CTA per row
__global__ void k_sig(const float* __restrict__ adj) {
    __shared__ float red[8];
    int row = blockIdx.x, t = threadIdx.x;
    const float4* src = (const float4*)(adj + (size_t)row * NN);
    uint2* dst = (uint2*)(g_S + (size_t)row * NN);
    float s = 0.f;
#pragma unroll
    for (int k = 0; k < 8; k++) {
        int idx = t + 256 * k;
        float4 v = src[idx];
        float s0 = sigf(v.x), s1 = sigf(v.y), s2 = sigf(v.z), s3 = sigf(v.w);
        s += (s0 + s1) + (s2 + s3);
        __nv_bfloat162 b0 = __floats2bfloat162_rn(s0, s1);
        __nv_bfloat162 b1 = __floats2bfloat162_rn(s2, s3);
        uint2 w; w.x = *(unsigned*)&b0; w.y = *(unsigned*)&b1;
        dst[idx] = w;
    }
#pragma unroll
    for (int d = 16; d; d >>= 1) s += __shfl_xor_sync(~0u, s, d);
    if ((t & 31) == 0) red[t >> 5] = s;
    __syncthreads();
    if (t == 0) {
        float tot = 0.f;
#pragma unroll
        for (int w = 0; w < 8; w++) tot += red[w];
        g_dinv[row] = 1.f / (tot + 1e-8f);
    }
}

__global__ void k_tX(const float* __restrict__ X) {
    __shared__ float tile[32][33];
    int k0 = blockIdx.x * 32, i0 = blockIdx.y * 32;
    int tx = threadIdx.x, ty = threadIdx.y;
#pragma unroll
    for (int r = 0; r < 4; r++)
        tile[ty + 8 * r][tx] = X[(size_t)(i0 + ty + 8 * r) * FEAT + k0 + tx];
    __syncthreads();
#pragma unroll
    for (int r = 0; r < 4; r++)
        g_combT[(size_t)(k0 + ty + 8 * r) * NN + i0 + tx] =
            __uint_as_float(cvtf(tile[tx][ty + 8 * r]));
}

__global__ void k_oh(const float* __restrict__ oh) {
    int idx = blockIdx.x * 256 + threadIdx.x;
    int i = idx / C, c = idx - i * C;
    g_curB[(size_t)c * NN + i] = __float2bfloat16(oh[idx]);
}

__global__ void k_w1c(const float* __restrict__ W1) {
    int idx = blockIdx.x * 256 + threadIdx.x;
    g_W1t[idx] = cvtf(W1[idx]);
}

// hop GEMM: 4-stage cp.async (distance 3), K-chunk 64, single wave.
// grid(64,KSPL) x 256, dyn smem 96768
__global__ void __launch_bounds__(256, 2) k_hop_mma() {
    extern __shared__ __align__(16) char hsm[];
    int t = threadIdx.x, lane = t & 31, w = t >> 5;
    int m0 = blockIdx.x * 128, slice = blockIdx.y;
    float acc[5][4];
#pragma unroll
    for (int n = 0; n < 5; n++)
#pragma unroll
        for (int q = 0; q < 4; q++) acc[n][q] = 0.f;
    uint32_t sb = (uint32_t)__cvta_generic_to_shared(hsm);
    uint32_t bA[4], bB[4];
#pragma unroll
    for (int s = 0; s < 4; s++) { bA[s] = sb + s * 24192; bB[s] = bA[s] + 18432; }
    uint32_t a_off = (uint32_t)(((w * 16 + (lane & 15)) * 72 + (lane >> 4) * 8) * 2);

#define HOP_PF(st, k0c) do { \
    _Pragma("unroll") \
    for (int q = 0; q < 4; q++) { \
        int idx = t + 256 * q; int row = idx >> 3, g = idx & 7; \
        CPA(bA[st] + (row * 72 + g * 8) * 2, g_S + (size_t)(m0 + row) * NN + (k0c) + g * 8); \
    } \
    _Pragma("unroll") \
    for (int q = 0; q < 2; q++) { \
        int idx = t + 256 * q; \
        if (idx < 320) { int row = idx >> 3, g = idx & 7; \
            CPA(bB[st] + (row * 72 + g * 8) * 2, g_curB + (size_t)row * NN + (k0c) + g * 8); } \
    } } while (0)

    int kbase = slice * 2048;
    HOP_PF(0, kbase); CPCOMMIT();
    HOP_PF(1, kbase + 64); CPCOMMIT();
    HOP_PF(2, kbase + 128); CPCOMMIT();
    for (int ch = 0; ch < 32; ch++) {
        CPWAIT2();
        __syncthreads();
        if (ch + 3 < 32) HOP_PF((ch + 3) & 3, kbase + (ch + 3) * 64);
        CPCOMMIT();
        int cb = ch & 3;
        const __nv_bfloat16* B = (const __nv_bfloat16*)(hsm + cb * 24192 + 18432);
        uint32_t ab = bA[cb] + a_off;
#pragma unroll
        for (int ks = 0; ks < 4; ks++) {
            uint32_t a0, a1, a2, a3;
            asm volatile("ldmatrix.sync.aligned.m8n8.x4.shared.b16 {%0,%1,%2,%3}, [%4];"
                : "=r"(a0), "=r"(a1), "=r"(a2), "=r"(a3) : "r"(ab + ks * 32));
#pragma unroll
            for (int nt = 0; nt < 5; nt++) {
                const uint32_t* bp = (const uint32_t*)(B + (nt * 8 + (lane >> 2)) * 72
                                                       + ks * 16 + (lane & 3) * 2);
                uint32_t b0 = bp[0], b1 = bp[4];
                asm volatile("mma.sync.aligned.m16n8k16.row.col.f32.bf16.bf16.f32 "
                    "{%0,%1,%2,%3}, {%4,%5,%6,%7}, {%8,%9}, {%0,%1,%2,%3};"
                    : "+f"(acc[nt][0]), "+f"(acc[nt][1]), "+f"(acc[nt][2]), "+f"(acc[nt][3])
                    : "r"(a0), "r"(a1), "r"(a2), "r"(a3), "r"(b0), "r"(b1));
            }
        }
    }
    int r1 = m0 + w * 16 + (lane >> 2);
    int cc = (lane & 3) * 2;
#pragma unroll
    for (int nt = 0; nt < 5; nt++) {
        *(float2*)(g_part + ((size_t)slice * NN + r1) * C + nt * 8 + cc)
            = make_float2(acc[nt][0], acc[nt][1]);
        *(float2*)(g_part + ((size_t)slice * NN + r1 + 8) * C + nt * 8 + cc)
            = make_float2(acc[nt][2], acc[nt][3]);
    }
}

// reduce partials + d_inv + softmax -> combT(tf32-rounded) + curB bf16
__global__ void k_hop_epi(int hop) {
    int i = blockIdx.x * 256 + threadIdx.x;
    float v[C];
#pragma unroll
    for (int c = 0; c < C; c++) v[c] = 0.f;
#pragma unroll
    for (int s = 0; s < KSPL; s++) {
        const float4* p4 = (const float4*)(g_part + ((size_t)s * NN + i) * C);
#pragma unroll
        for (int q = 0; q < 10; q++) {
            float4 w = p4[q];
            v[4*q] += w.x; v[4*q+1] += w.y; v[4*q+2] += w.z; v[4*q+3] += w.w;
        }
    }
    float di = g_dinv[i], m = -1e30f;
#pragma unroll
    for (int c = 0; c < C; c++) { v[c] *= di; m = fmaxf(m, v[c]); }
    float sum = 0.f;
#pragma unroll
    for (int c = 0; c < C; c++) { v[c] = __expf(v[c] - m); sum += v[c]; }
    float inv = 1.f / sum;
    float* ob = g_combT + (size_t)(FEAT + hop * C) * NN + i;
#pragma unroll
    for (int c = 0; c < C; c++) {
        float r = v[c] * inv;
        ob[c * NN] = __uint_as_float(cvtf(r));
        if (hop < 3) g_curB[(size_t)c * NN + i] = __float2bfloat16(r);
    }
}

// MLP1 tf32 mma, persistent 2 i-tiles per CTA: grid(32,8) x 256, dyn smem 67584B
__global__ void __launch_bounds__(256, 2) k_mlp1(const float* __restrict__ b1) {
    extern __shared__ float dsm[];
    int t = threadIdx.x, lane = t & 31, w = t >> 5;
    int o0 = blockIdx.y * 128;
    int wi = (w & 3) * 32, wo = (w >> 2) * 64;
    int t4 = lane & 3, g8 = lane >> 2;
    uint32_t sb0 = (uint32_t)__cvta_generic_to_shared(dsm);

#define M1_PF(st, k0) do { \
    uint32_t ba = sb0 + (st) * 8448 * 4; \
    _Pragma("unroll") \
    for (int q = 0; q < 4; q++) { \
        int idx = t + 256 * q; int row = idx >> 5, g = idx & 31; \
        CPA(ba + (row * 132 + g * 4) * 4, g_combT + (size_t)((k0) + row) * NN + i0 + g * 4); \
        CPA(ba + (4224 + row * 132 + g * 4) * 4, g_W1t + (size_t)((k0) + row) * HID + o0 + g * 4); \
    } } while (0)

    for (int rep = 0; rep < 2; rep++) {
        int i0 = (blockIdx.x + rep * 32) * 128;
        float acc[2][8][4];
#pragma unroll
        for (int mt = 0; mt < 2; mt++)
#pragma unroll
            for (int nt = 0; nt < 8; nt++)
#pragma unroll
                for (int q = 0; q < 4; q++) acc[mt][nt][q] = 0.f;

        M1_PF(0, 0);
        CPCOMMIT();
        for (int ck = 0; ck < 21; ck++) {
            CPWAIT0();
            __syncthreads();
            if (ck < 20) { M1_PF((ck + 1) & 1, (ck + 1) * 32); CPCOMMIT(); }
            const uint32_t* A = (const uint32_t*)(dsm + (ck & 1) * 8448);
            const uint32_t* Bs = A + 4224;
#pragma unroll
            for (int ks = 0; ks < 4; ks++) {
                int kr = ks * 8;
                uint32_t bF[8][2];
#pragma unroll
                for (int nt = 0; nt < 8; nt++) {
                    bF[nt][0] = Bs[(kr + t4) * 132 + wo + nt * 8 + g8];
                    bF[nt][1] = Bs[(kr + t4 + 4) * 132 + wo + nt * 8 + g8];
                }
#pragma unroll
                for (int mt = 0; mt < 2; mt++) {
                    int ib = wi + mt * 16 + g8;
                    uint32_t a0 = A[(kr + t4) * 132 + ib];
                    uint32_t a1 = A[(kr + t4) * 132 + ib + 8];
                    uint32_t a2 = A[(kr + t4 + 4) * 132 + ib];
                    uint32_t a3 = A[(kr + t4 + 4) * 132 + ib + 8];
#pragma unroll
                    for (int nt = 0; nt < 8; nt++) {
                        asm volatile("mma.sync.aligned.m16n8k8.row.col.f32.tf32.tf32.f32 "
                            "{%0,%1,%2,%3}, {%4,%5,%6,%7}, {%8,%9}, {%0,%1,%2,%3};"
                            : "+f"(acc[mt][nt][0]), "+f"(acc[mt][nt][1]),
                              "+f"(acc[mt][nt][2]), "+f"(acc[mt][nt][3])
                            : "r"(a0), "r"(a1), "r"(a2), "r"(a3),
                              "r"(bF[nt][0]), "r"(bF[nt][1]));
                    }
                }
            }
        }
        __syncthreads();
        float* dt = dsm;   // [o][130]
#pragma unroll
        for (int mt = 0; mt < 2; mt++)
#pragma unroll
            for (int nt = 0; nt < 8; nt++) {
                int i_ = wi + mt * 16 + g8, o_ = wo + nt * 8 + 2 * t4;
                dt[o_ * 130 + i_] = acc[mt][nt][0];
                dt[(o_ + 1) * 130 + i_] = acc[mt][nt][1];
                dt[o_ * 130 + i_ + 8] = acc[mt][nt][2];
                dt[(o_ + 1) * 130 + i_ + 8] = acc[mt][nt][3];
            }
        __syncthreads();
        for (int idx = t; idx < 16384; idx += 256) {
            int o = idx >> 7, i = idx & 127;
            float v = dt[o * 130 + i] + b1[o0 + o];
            g_hT[(size_t)(o0 + o) * NN + i0 + i] = fmaxf(v, 0.f);
        }
        __syncthreads();   // dsm reused by next rep's prefetch
    }
}

__global__ void __launch_bounds__(256, 2) k_mlp2(const float* __restrict__ W2) {
    __shared__ float s_w[128 * 40];
    int t = threadIdx.x, os = blockIdx.x;
    int i = blockIdx.y * 256 + t, o0 = os * 128;
    ull acc[20];
#pragma unroll
    for (int p = 0; p < 20; p++) acc[p] = 0;
    const float4* w4 = (const float4*)W2;
#pragma unroll
    for (int idx = t; idx < 128 * 10; idx += 256)
        ((float4*)s_w)[idx] = w4[(size_t)o0 * 10 + idx];
    __syncthreads();
    const float* hb = g_hT + (size_t)o0 * NN + i;
#pragma unroll 2
    for (int o = 0; o < 128; o++) {
        float x = hb[(size_t)o * NN];
        ull x2 = pack2(x, x);
        const ull* wr = (const ull*)(s_w + o * 40);
#pragma unroll
        for (int p = 0; p < 20; p++) ffma2(acc[p], x2, wr[p]);
    }
    ull* ob = (ull*)(g_part + ((size_t)os * NN + i) * C);
#pragma unroll
    for (int p = 0; p < 20; p++) ob[p] = acc[p];
}

__global__ void k_outf(const float* __restrict__ b2, float* __restrict__ out) {
    int i = blockIdx.x * 256 + threadIdx.x;
    float v[C];
#pragma unroll
    for (int c = 0; c < C; c++) v[c] = b2[c];
#pragma unroll
    for (int s = 0; s < OSPLIT2; s++) {
        const float4* p4 = (const float4*)(g_part + ((size_t)s * NN + i) * C);
#pragma unroll
        for (int q = 0; q < 10; q++) {
            float4 w = p4[q];
            v[4*q] += w.x; v[4*q+1] += w.y; v[4*q+2] += w.z; v[4*q+3] += w.w;
        }
    }
    float4* ob = (float4*)(out + (size_t)i * C);
#pragma unroll
    for (int q = 0; q < 10; q++)
        ob[q] = make_float4(v[4*q], v[4*q+1], v[4*q+2], v[4*q+3]);
}

extern "C" void kernel_launch(void* const* d_in, const int* in_sizes, int n_in,
                              void* d_out, int out_size) {
    const float* X   = (const float*)d_in[0];
    const float* oh  = (const float*)d_in[1];
    const float* adj = (const float*)d_in[2];
    const float* W1  = (const float*)d_in[3];
    const float* b1  = (const float*)d_in[4];
    const float* W2  = (const float*)d_in[5];
    const float* b2  = (const float*)d_in[6];
    float* out = (float*)d_out;

    cudaFuncSetAttribute(k_hop_mma, cudaFuncAttributeMaxDynamicSharedMemorySize, 96768);
    cudaFuncSetAttribute(k_mlp1, cudaFuncAttributeMaxDynamicSharedMemorySize, 67584);

    k_sig<<<8192, 256>>>(adj);
    k_tX<<<dim3(16, 256), dim3(32, 8)>>>(X);
    k_oh<<<1280, 256>>>(oh);
    k_w1c<<<2688, 256>>>(W1);
    for (int hop = 0; hop < 4; hop++) {
        k_hop_mma<<<dim3(64, KSPL), 256, 96768>>>();
        k_hop_epi<<<32, 256>>>(hop);
    }
    k_mlp1<<<dim3(32, 8), 256, 67584>>>(b1);
    k_mlp2<<<dim3(OSPLIT2, 32), 256>>>(W2);
    k_outf<<<32, 256>>>(b2, out);
}